// round 9
// baseline (speedup 1.0000x reference)
#include <cuda_runtime.h>
#include <cstdint>
#include <cstddef>

#define N_NODES 50000

// ---------------- scratch (device globals: no allocation allowed) ----------------
__device__ __align__(256) float g_P1[N_NODES * 64];
__device__ __align__(256) float g_R1[N_NODES * 64];
__device__ __align__(256) float g_P2[N_NODES * 64];
__device__ __align__(256) float g_R2[N_NODES * 64];
__device__ __align__(256) float g_H[N_NODES * 128];   // bands h0|h1 (h2 never hits global)
__device__ __align__(256) float g_U[N_NODES * 64];
__device__ __align__(256) float g_V[N_NODES * 64];
__device__ __align__(256) float g_deginv[N_NODES];
__device__ __align__(256) int   g_cnt[N_NODES];
__device__ __align__(256) int   g_off[N_NODES];
__device__ __align__(256) int   g_cur[N_NODES];
__device__ __align__(256) int   g_adj[800000];

// ---------------- CSR build ----------------
__global__ void zero_int_kernel(int* __restrict__ p, int n) {
    int i = blockIdx.x * blockDim.x + threadIdx.x;
    if (i < n) p[i] = 0;
}

__global__ void count_deg_kernel(const int4* __restrict__ dst4, int* __restrict__ cnt, int E4) {
    int i = blockIdx.x * blockDim.x + threadIdx.x;
    if (i < E4) {
        int4 d = __ldg(dst4 + i);
        atomicAdd(&cnt[d.x], 1);
        atomicAdd(&cnt[d.y], 1);
        atomicAdd(&cnt[d.z], 1);
        atomicAdd(&cnt[d.w], 1);
    }
}

__global__ __launch_bounds__(1024) void scan_all_kernel(
    const int* __restrict__ cnt, int* __restrict__ off, int* __restrict__ cur,
    float* __restrict__ deginv, int n)
{
    __shared__ int sh[1024];
    const int tid = threadIdx.x;
    const int CH = (n + 1023) / 1024;
    const int base = tid * CH;
    int s = 0;
    for (int i = 0; i < CH; i++) {
        int idx = base + i;
        if (idx < n) s += cnt[idx];
    }
    sh[tid] = s;
    __syncthreads();
#pragma unroll
    for (int d = 1; d < 1024; d <<= 1) {
        int t = (tid >= d) ? sh[tid - d] : 0;
        __syncthreads();
        sh[tid] += t;
        __syncthreads();
    }
    int run = sh[tid] - s;
    for (int i = 0; i < CH; i++) {
        int idx = base + i;
        if (idx < n) {
            int c = cnt[idx];
            off[idx] = run;
            cur[idx] = run;
            deginv[idx] = 1.0f / fmaxf((float)c, 1.0f);
            run += c;
        }
    }
}

__global__ void fill_kernel(const int* __restrict__ src, const int* __restrict__ dst,
                            int* __restrict__ cur, int* __restrict__ adj, int E) {
    int e = blockIdx.x * blockDim.x + threadIdx.x;
    if (e >= E) return;
    int d = dst[e];
    int pos = atomicAdd(&cur[d], 1);
    adj[pos] = src[e];
}

// ---------------- tf32 helpers ----------------
__device__ __forceinline__ uint2 split_tf32(float x) {
    unsigned hi, lo;
    asm("cvt.rna.tf32.f32 %0, %1;" : "=r"(hi) : "f"(x));
    float r = x - __uint_as_float(hi);
    asm("cvt.rna.tf32.f32 %0, %1;" : "=r"(lo) : "f"(r));
    return make_uint2(hi, lo);
}

__device__ __forceinline__ void mma8(float* d, unsigned a0, unsigned a1,
                                     unsigned a2, unsigned a3,
                                     unsigned b0, unsigned b1) {
    asm volatile(
        "mma.sync.aligned.m16n8k8.row.col.f32.tf32.tf32.f32 "
        "{%0,%1,%2,%3}, {%4,%5,%6,%7}, {%8,%9}, {%0,%1,%2,%3};"
        : "+f"(d[0]), "+f"(d[1]), "+f"(d[2]), "+f"(d[3])
        : "r"(a0), "r"(a1), "r"(a2), "r"(a3), "r"(b0), "r"(b1));
}

#define TBK 16
#define SROW 18
#define ATILE (128 * SROW)
#define HSM_W 68

__device__ __forceinline__ void stash(uint2* base, int row, int kq, float4 v) {
    uint2* p = base + row * SROW + kq * 4;
    p[0] = split_tf32(v.x);
    p[1] = split_tf32(v.y);
    p[2] = split_tf32(v.z);
    p[3] = split_tf32(v.w);
}

// ---------------- standalone dual GEMM for layer 0 (A from global x) ----------------
__global__ __launch_bounds__(256, 2) void gemm_dual_tc(
    const float* __restrict__ A, int lda, int K,
    const float* __restrict__ Wt, const float* __restrict__ Wb, int wld,
    float* __restrict__ Ot, float* __restrict__ Ob, int nNodes)
{
    extern __shared__ uint2 smem_u2[];
    uint2* Ash = smem_u2;
    uint2* Wsh = smem_u2 + 2 * ATILE;

    const int t = threadIdx.x;
    const int lane = t & 31, warp = t >> 5;
    const int grp = lane >> 2, tig = lane & 3;
    const int warpM = warp >> 1, warpN = warp & 1;
    const int m0 = blockIdx.x * 128;

    const int lm = t >> 2;
    const int lkq = t & 3;
    const int ar0 = min(m0 + lm, nNodes - 1);
    const int ar1 = min(m0 + lm + 64, nNodes - 1);
    const float* aptr0 = A + (size_t)ar0 * lda + lkq * 4;
    const float* aptr1 = A + (size_t)ar1 * lda + lkq * 4;
    const float* wptr0 = Wt + (size_t)lm * wld + lkq * 4;
    const float* wptr1 = Wb + (size_t)lm * wld + lkq * 4;

    float acc[2][8][4];
#pragma unroll
    for (int mt = 0; mt < 2; mt++)
#pragma unroll
        for (int nt = 0; nt < 8; nt++)
#pragma unroll
            for (int j = 0; j < 4; j++) acc[mt][nt][j] = 0.f;

    const int ntiles = K / TBK;

    float4 pa0 = *(const float4*)(aptr0);
    float4 pa1 = *(const float4*)(aptr1);
    float4 pw0 = *(const float4*)(wptr0);
    float4 pw1 = *(const float4*)(wptr1);
    stash(Ash, lm, lkq, pa0);
    stash(Ash, lm + 64, lkq, pa1);
    stash(Wsh, lm, lkq, pw0);
    stash(Wsh, lm + 64, lkq, pw1);
    __syncthreads();

    for (int tt = 0; tt < ntiles; tt++) {
        const int cur = tt & 1;
        const bool more = (tt + 1 < ntiles);
        if (more) {
            const int ko = (tt + 1) * TBK;
            pa0 = *(const float4*)(aptr0 + ko);
            pa1 = *(const float4*)(aptr1 + ko);
            pw0 = *(const float4*)(wptr0 + ko);
            pw1 = *(const float4*)(wptr1 + ko);
        }
        const uint2* Ab = Ash + cur * ATILE;
        const uint2* Wc = Wsh + cur * ATILE;
#pragma unroll
        for (int ks = 0; ks < 2; ks++) {
            const int kb = ks * 8;
            uint2 af[2][4];
#pragma unroll
            for (int mt = 0; mt < 2; mt++) {
                const uint2* ap = Ab + (warpM * 32 + mt * 16 + grp) * SROW + kb + tig;
                af[mt][0] = ap[0];
                af[mt][1] = ap[8 * SROW];
                af[mt][2] = ap[4];
                af[mt][3] = ap[8 * SROW + 4];
            }
#pragma unroll
            for (int nt = 0; nt < 8; nt++) {
                const uint2* wp = Wc + (warpN * 64 + nt * 8 + grp) * SROW + kb + tig;
                const uint2 b0 = wp[0];
                const uint2 b1 = wp[4];
#pragma unroll
                for (int mt = 0; mt < 2; mt++) {
                    mma8(acc[mt][nt], af[mt][0].x, af[mt][1].x, af[mt][2].x, af[mt][3].x, b0.x, b1.x);
                    mma8(acc[mt][nt], af[mt][0].y, af[mt][1].y, af[mt][2].y, af[mt][3].y, b0.x, b1.x);
                }
            }
        }
        if (more) {
            const int nxt = cur ^ 1;
            stash(Ash + nxt * ATILE, lm, lkq, pa0);
            stash(Ash + nxt * ATILE, lm + 64, lkq, pa1);
            stash(Wsh + nxt * ATILE, lm, lkq, pw0);
            stash(Wsh + nxt * ATILE, lm + 64, lkq, pw1);
        }
        __syncthreads();
    }

    float* O = warpN ? Ob : Ot;
#pragma unroll
    for (int mt = 0; mt < 2; mt++) {
#pragma unroll
        for (int nt = 0; nt < 8; nt++) {
            const int r0 = m0 + warpM * 32 + mt * 16 + grp;
            const int r1 = r0 + 8;
            const int col = nt * 8 + tig * 2;
            if (r0 < nNodes)
                *(float2*)(O + (size_t)r0 * 64 + col) = make_float2(acc[mt][nt][0], acc[mt][nt][1]);
            if (r1 < nNodes)
                *(float2*)(O + (size_t)r1 * 64 + col) = make_float2(acc[mt][nt][2], acc[mt][nt][3]);
        }
    }
}

#define GEMM_SMEM (4 * ATILE * (int)sizeof(uint2))              // 73728
#define FUSED_SMEM (128 * HSM_W * 4 + 4 * ATILE * (int)sizeof(uint2))  // 108544

// ---------------- fused: gather+combine (h) then GEMM h(@+H) x {Wt,Wb} ----------------
// KK=64 (layers): A = h (smem).  KK=192 (FINAL): A = [H cols 0..128 | h].
template<int KK, bool FINAL>
__global__ __launch_bounds__(256, 2) void sage_fused(
    const float* __restrict__ P, const float* __restrict__ Rin,
    const float* __restrict__ bl,
    const int* __restrict__ adj, const int* __restrict__ off,
    const int* __restrict__ cnt, const float* __restrict__ deginv,
    float* __restrict__ H, int hcol,
    const float* __restrict__ Wt, const float* __restrict__ Wb, int wld,
    float* __restrict__ Ot, float* __restrict__ Ob, int nNodes)
{
    extern __shared__ char smraw[];
    float* hsm = (float*)smraw;                                // 128 x HSM_W floats
    uint2* Ash = (uint2*)(smraw + 128 * HSM_W * 4);
    uint2* Wsh = Ash + 2 * ATILE;

    const int t = threadIdx.x;
    const int m0 = blockIdx.x * 128;

    // ---- Phase A: gather + combine -> hsm (+ global H band for non-final) ----
    {
        const int r = t >> 1;           // 0..127
        const int half = t & 1;         // 32-float half of the row
        const int node = min(m0 + r, nNodes - 1);
        const int beg = __ldg(off + node);
        const int c = __ldg(cnt + node);
        const float4* Pb = (const float4*)P + half * 8;
        float4 acc[8];
#pragma unroll
        for (int k = 0; k < 8; k++) acc[k] = make_float4(0.f, 0.f, 0.f, 0.f);
        for (int j = 0; j < c; j++) {
            int s = __ldg(adj + beg + j);
            const float4* pp = Pb + (size_t)s * 16;
#pragma unroll
            for (int k = 0; k < 8; k++) {
                float4 v = __ldg(pp + k);
                acc[k].x += v.x; acc[k].y += v.y; acc[k].z += v.z; acc[k].w += v.w;
            }
        }
        const float di = __ldg(deginv + node);
        const float4* rr = (const float4*)(Rin + (size_t)node * 64 + half * 32);
        const float4* bb = (const float4*)(bl + half * 32);
        float* hrow = hsm + r * HSM_W + half * 32;
#pragma unroll
        for (int k = 0; k < 8; k++) {
            float4 rv = __ldg(rr + k);
            float4 bv = __ldg(bb + k);
            float4 h;
            h.x = fmaxf(fmaf(acc[k].x, di, bv.x) + rv.x, 0.f);
            h.y = fmaxf(fmaf(acc[k].y, di, bv.y) + rv.y, 0.f);
            h.z = fmaxf(fmaf(acc[k].z, di, bv.z) + rv.z, 0.f);
            h.w = fmaxf(fmaf(acc[k].w, di, bv.w) + rv.w, 0.f);
            *(float4*)(hrow + k * 4) = h;
            if (!FINAL)
                *(float4*)(H + (size_t)node * 128 + hcol + half * 32 + k * 4) = h;
        }
    }
    __syncthreads();

    // ---- Phase B: pipelined GEMM over KK ----
    const int lane = t & 31, warp = t >> 5;
    const int grp = lane >> 2, tig = lane & 3;
    const int warpM = warp >> 1, warpN = warp & 1;
    const int lm = t >> 2;
    const int lkq = t & 3;
    const float* wptr0 = Wt + (size_t)lm * wld + lkq * 4;
    const float* wptr1 = Wb + (size_t)lm * wld + lkq * 4;

    auto loadA = [&](int row, int ko) -> float4 {
        const int col = ko + lkq * 4;
        if (FINAL) {
            if (col < 128) {
                const int g = min(m0 + row, nNodes - 1);
                return *(const float4*)(H + (size_t)g * 128 + col);
            }
            return *(const float4*)(hsm + row * HSM_W + (col - 128));
        }
        return *(const float4*)(hsm + row * HSM_W + col);
    };

    float acc[2][8][4];
#pragma unroll
    for (int mt = 0; mt < 2; mt++)
#pragma unroll
        for (int nt = 0; nt < 8; nt++)
#pragma unroll
            for (int j = 0; j < 4; j++) acc[mt][nt][j] = 0.f;

    const int ntiles = KK / TBK;

    float4 pa0 = loadA(lm, 0);
    float4 pa1 = loadA(lm + 64, 0);
    float4 pw0 = *(const float4*)(wptr0);
    float4 pw1 = *(const float4*)(wptr1);
    stash(Ash, lm, lkq, pa0);
    stash(Ash, lm + 64, lkq, pa1);
    stash(Wsh, lm, lkq, pw0);
    stash(Wsh, lm + 64, lkq, pw1);
    __syncthreads();

    for (int tt = 0; tt < ntiles; tt++) {
        const int cur = tt & 1;
        const bool more = (tt + 1 < ntiles);
        if (more) {
            const int ko = (tt + 1) * TBK;
            pa0 = loadA(lm, ko);
            pa1 = loadA(lm + 64, ko);
            pw0 = *(const float4*)(wptr0 + ko);
            pw1 = *(const float4*)(wptr1 + ko);
        }
        const uint2* Ab = Ash + cur * ATILE;
        const uint2* Wc = Wsh + cur * ATILE;
#pragma unroll
        for (int ks = 0; ks < 2; ks++) {
            const int kb = ks * 8;
            uint2 af[2][4];
#pragma unroll
            for (int mt = 0; mt < 2; mt++) {
                const uint2* ap = Ab + (warpM * 32 + mt * 16 + grp) * SROW + kb + tig;
                af[mt][0] = ap[0];
                af[mt][1] = ap[8 * SROW];
                af[mt][2] = ap[4];
                af[mt][3] = ap[8 * SROW + 4];
            }
#pragma unroll
            for (int nt = 0; nt < 8; nt++) {
                const uint2* wp = Wc + (warpN * 64 + nt * 8 + grp) * SROW + kb + tig;
                const uint2 b0 = wp[0];
                const uint2 b1 = wp[4];
#pragma unroll
                for (int mt = 0; mt < 2; mt++) {
                    mma8(acc[mt][nt], af[mt][0].x, af[mt][1].x, af[mt][2].x, af[mt][3].x, b0.x, b1.x);
                    mma8(acc[mt][nt], af[mt][0].y, af[mt][1].y, af[mt][2].y, af[mt][3].y, b0.x, b1.x);
                }
            }
        }
        if (more) {
            const int nxt = cur ^ 1;
            stash(Ash + nxt * ATILE, lm, lkq, pa0);
            stash(Ash + nxt * ATILE, lm + 64, lkq, pa1);
            stash(Wsh + nxt * ATILE, lm, lkq, pw0);
            stash(Wsh + nxt * ATILE, lm + 64, lkq, pw1);
        }
        __syncthreads();
    }

    float* O = warpN ? Ob : Ot;
#pragma unroll
    for (int mt = 0; mt < 2; mt++) {
#pragma unroll
        for (int nt = 0; nt < 8; nt++) {
            const int r0 = m0 + warpM * 32 + mt * 16 + grp;
            const int r1 = r0 + 8;
            const int col = nt * 8 + tig * 2;
            if (r0 < nNodes)
                *(float2*)(O + (size_t)r0 * 64 + col) = make_float2(acc[mt][nt][0], acc[mt][nt][1]);
            if (r1 < nNodes)
                *(float2*)(O + (size_t)r1 * 64 + col) = make_float2(acc[mt][nt][2], acc[mt][nt][3]);
        }
    }
}

// ---------------- edge head ----------------
__global__ __launch_bounds__(256) void edge_kernel(
    const float* __restrict__ U, const float* __restrict__ V,
    const int* __restrict__ src, const int* __restrict__ dst,
    const float* __restrict__ bm1, const float* __restrict__ Wm2,
    const float* __restrict__ bm2, float* __restrict__ out, int E)
{
    __shared__ float bsh[64];
    __shared__ float wsh[64];
    int t = threadIdx.x;
    if (t < 64)       bsh[t]      = bm1[t];
    else if (t < 128) wsh[t - 64] = Wm2[t - 64];
    __syncthreads();

    int e = blockIdx.x * blockDim.x + t;
    if (e >= E) return;
    int s = __ldg(src + e);
    int d = __ldg(dst + e);
    const float4* up = (const float4*)(U + (size_t)s * 64);
    const float4* vp = (const float4*)(V + (size_t)d * 64);
    float acc = __ldg(bm2);
#pragma unroll 4
    for (int j = 0; j < 16; j++) {
        float4 u = __ldg(up + j);
        float4 v = __ldg(vp + j);
        float4 b = *(const float4*)&bsh[j * 4];
        float4 w = *(const float4*)&wsh[j * 4];
        acc += fmaxf(u.x + v.x + b.x, 0.f) * w.x;
        acc += fmaxf(u.y + v.y + b.y, 0.f) * w.y;
        acc += fmaxf(u.z + v.z + b.z, 0.f) * w.z;
        acc += fmaxf(u.w + v.w + b.w, 0.f) * w.w;
    }
    out[e] = acc;
}

// ---------------- host launcher ----------------
extern "C" void kernel_launch(void* const* d_in, const int* in_sizes, int n_in,
                              void* d_out, int out_size)
{
    const float* x   = (const float*)d_in[0];
    const int*   src = (const int*)d_in[1];
    const int*   dst = (const int*)d_in[2];
    const float* Wl0 = (const float*)d_in[3];
    const float* bl0 = (const float*)d_in[4];
    const float* Wr0 = (const float*)d_in[5];
    const float* Wl1 = (const float*)d_in[6];
    const float* bl1 = (const float*)d_in[7];
    const float* Wr1 = (const float*)d_in[8];
    const float* Wl2 = (const float*)d_in[9];
    const float* bl2 = (const float*)d_in[10];
    const float* Wr2 = (const float*)d_in[11];
    const float* Wm1 = (const float*)d_in[12];
    const float* bm1 = (const float*)d_in[13];
    const float* Wm2 = (const float*)d_in[14];
    const float* bm2 = (const float*)d_in[15];
    float* out = (float*)d_out;
    const int E = in_sizes[1];

    void* p;
    cudaGetSymbolAddress(&p, g_P1);     float* P1     = (float*)p;
    cudaGetSymbolAddress(&p, g_R1);     float* R1     = (float*)p;
    cudaGetSymbolAddress(&p, g_P2);     float* P2     = (float*)p;
    cudaGetSymbolAddress(&p, g_R2);     float* R2     = (float*)p;
    cudaGetSymbolAddress(&p, g_H);      float* H      = (float*)p;
    cudaGetSymbolAddress(&p, g_U);      float* U      = (float*)p;
    cudaGetSymbolAddress(&p, g_V);      float* V      = (float*)p;
    cudaGetSymbolAddress(&p, g_deginv); float* deginv = (float*)p;
    cudaGetSymbolAddress(&p, g_cnt);    int*   cnt    = (int*)p;
    cudaGetSymbolAddress(&p, g_off);    int*   off    = (int*)p;
    cudaGetSymbolAddress(&p, g_cur);    int*   cur    = (int*)p;
    cudaGetSymbolAddress(&p, g_adj);    int*   adj    = (int*)p;

    cudaFuncSetAttribute(gemm_dual_tc, cudaFuncAttributeMaxDynamicSharedMemorySize, GEMM_SMEM);
    cudaFuncSetAttribute(sage_fused<64, false>, cudaFuncAttributeMaxDynamicSharedMemorySize, FUSED_SMEM);
    cudaFuncSetAttribute(sage_fused<192, true>, cudaFuncAttributeMaxDynamicSharedMemorySize, FUSED_SMEM);

    const int T = 256;
    const int blocks128 = (N_NODES + 127) / 128;   // 391

    // ---- CSR build ----
    zero_int_kernel<<<(N_NODES + T - 1) / T, T>>>(cnt, N_NODES);
    count_deg_kernel<<<(E / 4 + T - 1) / T, T>>>((const int4*)dst, cnt, E / 4);
    scan_all_kernel<<<1, 1024>>>(cnt, off, cur, deginv, N_NODES);
    fill_kernel<<<(E + T - 1) / T, T>>>(src, dst, cur, adj, E);

    // ---- layer 0 GEMM: x -> P1, R1 ----
    gemm_dual_tc<<<blocks128, 256, GEMM_SMEM>>>(x, 128, 128, Wl0, Wr0, 128, P1, R1, N_NODES);

    // ---- fused layer 1: combine(P1,R1,bl0) -> h0 (H band 0); gemm h0 -> P2, R2 ----
    sage_fused<64, false><<<blocks128, 256, FUSED_SMEM>>>(
        P1, R1, bl0, adj, off, cnt, deginv, H, 0, Wl1, Wr1, 64, P2, R2, N_NODES);

    // ---- fused layer 2: combine(P2,R2,bl1) -> h1 (H band 64); gemm h1 -> P1, R1 ----
    sage_fused<64, false><<<blocks128, 256, FUSED_SMEM>>>(
        P2, R2, bl1, adj, off, cnt, deginv, H, 64, Wl2, Wr2, 64, P1, R1, N_NODES);

    // ---- fused final: combine(P1,R1,bl2) -> h2 (smem only); gemm [H|h2] @ Wm1 -> U, V ----
    sage_fused<192, true><<<blocks128, 256, FUSED_SMEM>>>(
        P1, R1, bl2, adj, off, cnt, deginv, H, 0, Wm1, Wm1 + 192, 384, U, V, N_NODES);

    // ---- per-edge head ----
    edge_kernel<<<(E + T - 1) / T, T>>>(U, V, src, dst, bm1, Wm2, bm2, out, E);
}

// round 10
// speedup vs baseline: 1.3869x; 1.3869x over previous
#include <cuda_runtime.h>
#include <cstdint>
#include <cstddef>

#define N_NODES 50000

// ---------------- scratch (device globals: no allocation allowed) ----------------
__device__ __align__(256) float g_P[N_NODES * 64];
__device__ __align__(256) float g_R[N_NODES * 64];
__device__ __align__(256) float g_H[N_NODES * 192];
__device__ __align__(256) float g_U[N_NODES * 64];
__device__ __align__(256) float g_V[N_NODES * 64];
__device__ __align__(256) float g_deginv[N_NODES];
__device__ __align__(256) int   g_cnt[N_NODES];
__device__ __align__(256) int   g_off[N_NODES];
__device__ __align__(256) int   g_cur[N_NODES];
__device__ __align__(256) int   g_adj[800000];

// ---------------- CSR build ----------------
__global__ void zero_int_kernel(int* __restrict__ p, int n) {
    int i = blockIdx.x * blockDim.x + threadIdx.x;
    if (i < n) p[i] = 0;
}

__global__ void count_deg_kernel(const int4* __restrict__ dst4, int* __restrict__ cnt, int E4) {
    int i = blockIdx.x * blockDim.x + threadIdx.x;
    if (i < E4) {
        int4 d = __ldg(dst4 + i);
        atomicAdd(&cnt[d.x], 1);
        atomicAdd(&cnt[d.y], 1);
        atomicAdd(&cnt[d.z], 1);
        atomicAdd(&cnt[d.w], 1);
    }
}

__global__ __launch_bounds__(1024) void scan_all_kernel(
    const int* __restrict__ cnt, int* __restrict__ off, int* __restrict__ cur,
    float* __restrict__ deginv, int n)
{
    __shared__ int sh[1024];
    const int tid = threadIdx.x;
    const int CH = (n + 1023) / 1024;
    const int base = tid * CH;
    int s = 0;
    for (int i = 0; i < CH; i++) {
        int idx = base + i;
        if (idx < n) s += cnt[idx];
    }
    sh[tid] = s;
    __syncthreads();
#pragma unroll
    for (int d = 1; d < 1024; d <<= 1) {
        int t = (tid >= d) ? sh[tid - d] : 0;
        __syncthreads();
        sh[tid] += t;
        __syncthreads();
    }
    int run = sh[tid] - s;
    for (int i = 0; i < CH; i++) {
        int idx = base + i;
        if (idx < n) {
            int c = cnt[idx];
            off[idx] = run;
            cur[idx] = run;
            deginv[idx] = 1.0f / fmaxf((float)c, 1.0f);
            run += c;
        }
    }
}

__global__ void fill_kernel(const int* __restrict__ src, const int* __restrict__ dst,
                            int* __restrict__ cur, int* __restrict__ adj, int E) {
    int e = blockIdx.x * blockDim.x + threadIdx.x;
    if (e >= E) return;
    int d = dst[e];
    int pos = atomicAdd(&cur[d], 1);
    adj[pos] = src[e];
}

// ---------------- tf32 helpers ----------------
__device__ __forceinline__ uint2 split_tf32(float x) {
    unsigned hi, lo;
    asm("cvt.rna.tf32.f32 %0, %1;" : "=r"(hi) : "f"(x));
    float r = x - __uint_as_float(hi);
    asm("cvt.rna.tf32.f32 %0, %1;" : "=r"(lo) : "f"(r));
    return make_uint2(hi, lo);
}

__device__ __forceinline__ void mma8(float* d, unsigned a0, unsigned a1,
                                     unsigned a2, unsigned a3,
                                     unsigned b0, unsigned b1) {
    asm volatile(
        "mma.sync.aligned.m16n8k8.row.col.f32.tf32.tf32.f32 "
        "{%0,%1,%2,%3}, {%4,%5,%6,%7}, {%8,%9}, {%0,%1,%2,%3};"
        : "+f"(d[0]), "+f"(d[1]), "+f"(d[2]), "+f"(d[3])
        : "r"(a0), "r"(a1), "r"(a2), "r"(a3), "r"(b0), "r"(b1));
}

// ---------------- tensor-core dual-output GEMM (2-term tf32 split) ----------------
#define TBK 16
#define SROW 18
#define ATILE (128 * SROW)

__device__ __forceinline__ void stash(uint2* base, int row, int kq, float4 v) {
    uint2* p = base + row * SROW + kq * 4;
    p[0] = split_tf32(v.x);
    p[1] = split_tf32(v.y);
    p[2] = split_tf32(v.z);
    p[3] = split_tf32(v.w);
}

__global__ __launch_bounds__(256, 2) void gemm_dual_tc(
    const float* __restrict__ A, int lda, int K,
    const float* __restrict__ Wt, const float* __restrict__ Wb, int wld,
    float* __restrict__ Ot, float* __restrict__ Ob, int nNodes)
{
    extern __shared__ uint2 smem_u2[];
    uint2* Ash = smem_u2;
    uint2* Wsh = smem_u2 + 2 * ATILE;

    const int t = threadIdx.x;
    const int lane = t & 31, warp = t >> 5;
    const int grp = lane >> 2, tig = lane & 3;
    const int warpM = warp >> 1, warpN = warp & 1;
    const int m0 = blockIdx.x * 128;

    const int lm = t >> 2;
    const int lkq = t & 3;
    const int ar0 = min(m0 + lm, nNodes - 1);
    const int ar1 = min(m0 + lm + 64, nNodes - 1);
    const float* aptr0 = A + (size_t)ar0 * lda + lkq * 4;
    const float* aptr1 = A + (size_t)ar1 * lda + lkq * 4;
    const float* wptr0 = Wt + (size_t)lm * wld + lkq * 4;
    const float* wptr1 = Wb + (size_t)lm * wld + lkq * 4;

    float acc[2][8][4];
#pragma unroll
    for (int mt = 0; mt < 2; mt++)
#pragma unroll
        for (int nt = 0; nt < 8; nt++)
#pragma unroll
            for (int j = 0; j < 4; j++) acc[mt][nt][j] = 0.f;

    const int ntiles = K / TBK;

    float4 pa0 = *(const float4*)(aptr0);
    float4 pa1 = *(const float4*)(aptr1);
    float4 pw0 = *(const float4*)(wptr0);
    float4 pw1 = *(const float4*)(wptr1);
    stash(Ash, lm, lkq, pa0);
    stash(Ash, lm + 64, lkq, pa1);
    stash(Wsh, lm, lkq, pw0);
    stash(Wsh, lm + 64, lkq, pw1);
    __syncthreads();

    for (int tt = 0; tt < ntiles; tt++) {
        const int cur = tt & 1;
        const bool more = (tt + 1 < ntiles);
        if (more) {
            const int ko = (tt + 1) * TBK;
            pa0 = *(const float4*)(aptr0 + ko);
            pa1 = *(const float4*)(aptr1 + ko);
            pw0 = *(const float4*)(wptr0 + ko);
            pw1 = *(const float4*)(wptr1 + ko);
        }
        const uint2* Ab = Ash + cur * ATILE;
        const uint2* Wc = Wsh + cur * ATILE;
#pragma unroll
        for (int ks = 0; ks < 2; ks++) {
            const int kb = ks * 8;
            uint2 af[2][4];
#pragma unroll
            for (int mt = 0; mt < 2; mt++) {
                const uint2* ap = Ab + (warpM * 32 + mt * 16 + grp) * SROW + kb + tig;
                af[mt][0] = ap[0];
                af[mt][1] = ap[8 * SROW];
                af[mt][2] = ap[4];
                af[mt][3] = ap[8 * SROW + 4];
            }
#pragma unroll
            for (int nt = 0; nt < 8; nt++) {
                const uint2* wp = Wc + (warpN * 64 + nt * 8 + grp) * SROW + kb + tig;
                const uint2 b0 = wp[0];
                const uint2 b1 = wp[4];
#pragma unroll
                for (int mt = 0; mt < 2; mt++) {
                    // 2-term split: ah*bh + al*bh
                    mma8(acc[mt][nt], af[mt][0].x, af[mt][1].x, af[mt][2].x, af[mt][3].x, b0.x, b1.x);
                    mma8(acc[mt][nt], af[mt][0].y, af[mt][1].y, af[mt][2].y, af[mt][3].y, b0.x, b1.x);
                }
            }
        }
        if (more) {
            const int nxt = cur ^ 1;
            stash(Ash + nxt * ATILE, lm, lkq, pa0);
            stash(Ash + nxt * ATILE, lm + 64, lkq, pa1);
            stash(Wsh + nxt * ATILE, lm, lkq, pw0);
            stash(Wsh + nxt * ATILE, lm + 64, lkq, pw1);
        }
        __syncthreads();
    }

    float* O = warpN ? Ob : Ot;
#pragma unroll
    for (int mt = 0; mt < 2; mt++) {
#pragma unroll
        for (int nt = 0; nt < 8; nt++) {
            const int r0 = m0 + warpM * 32 + mt * 16 + grp;
            const int r1 = r0 + 8;
            const int col = nt * 8 + tig * 2;
            if (r0 < nNodes)
                *(float2*)(O + (size_t)r0 * 64 + col) = make_float2(acc[mt][nt][0], acc[mt][nt][1]);
            if (r1 < nNodes)
                *(float2*)(O + (size_t)r1 * 64 + col) = make_float2(acc[mt][nt][2], acc[mt][nt][3]);
        }
    }
}

#define GEMM_SMEM (4 * ATILE * (int)sizeof(uint2))   // 73728 bytes

// ---------------- CSR gather + combine ----------------
__global__ __launch_bounds__(256) void gather_combine(
    const float* __restrict__ P, const int* __restrict__ adj,
    const int* __restrict__ off, const int* __restrict__ cnt,
    const float* __restrict__ deginv, const float* __restrict__ R,
    const float* __restrict__ bl, float* __restrict__ H, int col, int n)
{
    int tid = blockIdx.x * blockDim.x + threadIdx.x;
    int nn = tid >> 4;
    int q  = tid & 15;
    if (nn >= n) return;
    const int beg = __ldg(off + nn);
    const int c   = __ldg(cnt + nn);
    const float4* Pq = (const float4*)P + q;

    float4 acc0 = make_float4(0.f, 0.f, 0.f, 0.f);
    float4 acc1 = make_float4(0.f, 0.f, 0.f, 0.f);
    int j = 0;
    for (; j + 2 <= c; j += 2) {
        int s0 = __ldg(adj + beg + j);
        int s1 = __ldg(adj + beg + j + 1);
        float4 v0 = __ldg(Pq + (size_t)s0 * 16);
        float4 v1 = __ldg(Pq + (size_t)s1 * 16);
        acc0.x += v0.x; acc0.y += v0.y; acc0.z += v0.z; acc0.w += v0.w;
        acc1.x += v1.x; acc1.y += v1.y; acc1.z += v1.z; acc1.w += v1.w;
    }
    if (j < c) {
        int s0 = __ldg(adj + beg + j);
        float4 v0 = __ldg(Pq + (size_t)s0 * 16);
        acc0.x += v0.x; acc0.y += v0.y; acc0.z += v0.z; acc0.w += v0.w;
    }
    acc0.x += acc1.x; acc0.y += acc1.y; acc0.z += acc1.z; acc0.w += acc1.w;

    const float di = __ldg(deginv + nn);
    const float4 r = *(const float4*)(R + (size_t)nn * 64 + q * 4);
    const float4 b = *(const float4*)(bl + q * 4);
    float4 h;
    h.x = fmaxf(fmaf(acc0.x, di, b.x) + r.x, 0.f);
    h.y = fmaxf(fmaf(acc0.y, di, b.y) + r.y, 0.f);
    h.z = fmaxf(fmaf(acc0.z, di, b.z) + r.z, 0.f);
    h.w = fmaxf(fmaf(acc0.w, di, b.w) + r.w, 0.f);
    *(float4*)(H + (size_t)nn * 192 + col + q * 4) = h;
}

// ---------------- edge head ----------------
__global__ __launch_bounds__(256) void edge_kernel(
    const float* __restrict__ U, const float* __restrict__ V,
    const int* __restrict__ src, const int* __restrict__ dst,
    const float* __restrict__ bm1, const float* __restrict__ Wm2,
    const float* __restrict__ bm2, float* __restrict__ out, int E)
{
    __shared__ float bsh[64];
    __shared__ float wsh[64];
    int t = threadIdx.x;
    if (t < 64)       bsh[t]      = bm1[t];
    else if (t < 128) wsh[t - 64] = Wm2[t - 64];
    __syncthreads();

    int e = blockIdx.x * blockDim.x + t;
    if (e >= E) return;
    int s = __ldg(src + e);
    int d = __ldg(dst + e);
    const float4* up = (const float4*)(U + (size_t)s * 64);
    const float4* vp = (const float4*)(V + (size_t)d * 64);
    float acc = __ldg(bm2);
#pragma unroll 4
    for (int j = 0; j < 16; j++) {
        float4 u = __ldg(up + j);
        float4 v = __ldg(vp + j);
        float4 b = *(const float4*)&bsh[j * 4];
        float4 w = *(const float4*)&wsh[j * 4];
        acc += fmaxf(u.x + v.x + b.x, 0.f) * w.x;
        acc += fmaxf(u.y + v.y + b.y, 0.f) * w.y;
        acc += fmaxf(u.z + v.z + b.z, 0.f) * w.z;
        acc += fmaxf(u.w + v.w + b.w, 0.f) * w.w;
    }
    out[e] = acc;
}

// ---------------- host launcher ----------------
extern "C" void kernel_launch(void* const* d_in, const int* in_sizes, int n_in,
                              void* d_out, int out_size)
{
    const float* x   = (const float*)d_in[0];
    const int*   src = (const int*)d_in[1];
    const int*   dst = (const int*)d_in[2];
    const float* Wl0 = (const float*)d_in[3];
    const float* bl0 = (const float*)d_in[4];
    const float* Wr0 = (const float*)d_in[5];
    const float* Wl1 = (const float*)d_in[6];
    const float* bl1 = (const float*)d_in[7];
    const float* Wr1 = (const float*)d_in[8];
    const float* Wl2 = (const float*)d_in[9];
    const float* bl2 = (const float*)d_in[10];
    const float* Wr2 = (const float*)d_in[11];
    const float* Wm1 = (const float*)d_in[12];
    const float* bm1 = (const float*)d_in[13];
    const float* Wm2 = (const float*)d_in[14];
    const float* bm2 = (const float*)d_in[15];
    float* out = (float*)d_out;
    const int E = in_sizes[1];

    void* p;
    cudaGetSymbolAddress(&p, g_P);      float* P      = (float*)p;
    cudaGetSymbolAddress(&p, g_R);      float* R      = (float*)p;
    cudaGetSymbolAddress(&p, g_H);      float* H      = (float*)p;
    cudaGetSymbolAddress(&p, g_U);      float* U      = (float*)p;
    cudaGetSymbolAddress(&p, g_V);      float* V      = (float*)p;
    cudaGetSymbolAddress(&p, g_deginv); float* deginv = (float*)p;
    cudaGetSymbolAddress(&p, g_cnt);    int*   cnt    = (int*)p;
    cudaGetSymbolAddress(&p, g_off);    int*   off    = (int*)p;
    cudaGetSymbolAddress(&p, g_cur);    int*   cur    = (int*)p;
    cudaGetSymbolAddress(&p, g_adj);    int*   adj    = (int*)p;

    cudaFuncSetAttribute(gemm_dual_tc, cudaFuncAttributeMaxDynamicSharedMemorySize, GEMM_SMEM);

    const int T = 256;
    const int gemm_blocks = (N_NODES + 127) / 128;
    const int gc_blocks   = (N_NODES * 16 + T - 1) / T;

    // ---- CSR build ----
    zero_int_kernel<<<(N_NODES + T - 1) / T, T>>>(cnt, N_NODES);
    count_deg_kernel<<<(E / 4 + T - 1) / T, T>>>((const int4*)dst, cnt, E / 4);
    scan_all_kernel<<<1, 1024>>>(cnt, off, cur, deginv, N_NODES);
    fill_kernel<<<(E + T - 1) / T, T>>>(src, dst, cur, adj, E);

    // ---- SAGE layer 0 ----
    gemm_dual_tc<<<gemm_blocks, 256, GEMM_SMEM>>>(x, 128, 128, Wl0, Wr0, 128, P, R, N_NODES);
    gather_combine<<<gc_blocks, T>>>(P, adj, off, cnt, deginv, R, bl0, H, 0, N_NODES);

    // ---- SAGE layer 1 ----
    gemm_dual_tc<<<gemm_blocks, 256, GEMM_SMEM>>>(H, 192, 64, Wl1, Wr1, 64, P, R, N_NODES);
    gather_combine<<<gc_blocks, T>>>(P, adj, off, cnt, deginv, R, bl1, H, 64, N_NODES);

    // ---- SAGE layer 2 ----
    gemm_dual_tc<<<gemm_blocks, 256, GEMM_SMEM>>>(H + 64, 192, 64, Wl2, Wr2, 64, P, R, N_NODES);
    gather_combine<<<gc_blocks, T>>>(P, adj, off, cnt, deginv, R, bl2, H, 128, N_NODES);

    // ---- edge MLP decomposition ----
    gemm_dual_tc<<<gemm_blocks, 256, GEMM_SMEM>>>(H, 192, 192, Wm1, Wm1 + 192, 384, U, V, N_NODES);

    // ---- per-edge head ----
    edge_kernel<<<(E + T - 1) / T, T>>>(U, V, src, dst, bm1, Wm2, bm2, out, E);
}

// round 12
// speedup vs baseline: 1.8271x; 1.3174x over previous
#include <cuda_runtime.h>
#include <cstdint>
#include <cstddef>

#define N_NODES 50000
#define SCAN_T 512
#define NSCAN_BLOCKS ((N_NODES + SCAN_T - 1) / SCAN_T)   // 98

// ---------------- scratch (device globals: no allocation allowed) ----------------
__device__ __align__(256) float g_P[N_NODES * 64];
__device__ __align__(256) float g_R[N_NODES * 64];
__device__ __align__(256) float g_H[N_NODES * 192];
__device__ __align__(256) float g_U[N_NODES * 64];
__device__ __align__(256) float g_V[N_NODES * 64];
__device__ __align__(256) float g_deginv[N_NODES];
__device__ __align__(256) int   g_cnt[N_NODES];
__device__ __align__(256) int   g_off[N_NODES];
__device__ __align__(256) int   g_cur[N_NODES];
__device__ __align__(256) int   g_bsum[128];
__device__ __align__(256) int   g_adj[800000];

// ---------------- CSR build (parallel 3-kernel scan, as measured in R3) ----------------
__global__ void zero_int_kernel(int* __restrict__ p, int n) {
    int i = blockIdx.x * blockDim.x + threadIdx.x;
    if (i < n) p[i] = 0;
}

__global__ void count_deg_kernel(const int* __restrict__ dst, int* __restrict__ cnt, int E) {
    int e = blockIdx.x * blockDim.x + threadIdx.x;
    if (e < E) atomicAdd(&cnt[dst[e]], 1);
}

__global__ void scan1_kernel(const int* __restrict__ cnt, int* __restrict__ off,
                             int* __restrict__ bsum, int n) {
    __shared__ int sh[SCAN_T];
    int tid = threadIdx.x;
    int i = blockIdx.x * SCAN_T + tid;
    int v = (i < n) ? cnt[i] : 0;
    sh[tid] = v;
    __syncthreads();
#pragma unroll
    for (int d = 1; d < SCAN_T; d <<= 1) {
        int t = (tid >= d) ? sh[tid - d] : 0;
        __syncthreads();
        sh[tid] += t;
        __syncthreads();
    }
    if (i < n) off[i] = sh[tid] - v;
    if (tid == SCAN_T - 1) bsum[blockIdx.x] = sh[tid];
}

__global__ void scan2_kernel(int* __restrict__ bsum, int nb) {
    __shared__ int sh[128];
    int tid = threadIdx.x;
    int v = (tid < nb) ? bsum[tid] : 0;
    sh[tid] = v;
    __syncthreads();
#pragma unroll
    for (int d = 1; d < 128; d <<= 1) {
        int t = (tid >= d) ? sh[tid - d] : 0;
        __syncthreads();
        sh[tid] += t;
        __syncthreads();
    }
    if (tid < nb) bsum[tid] = sh[tid] - v;
}

__global__ void scan3_kernel(int* __restrict__ off, int* __restrict__ cur,
                             const int* __restrict__ cnt, const int* __restrict__ bsum,
                             float* __restrict__ deginv, int n) {
    int i = blockIdx.x * blockDim.x + threadIdx.x;
    if (i >= n) return;
    int o = off[i] + bsum[i / SCAN_T];
    off[i] = o;
    cur[i] = o;
    deginv[i] = 1.0f / fmaxf((float)cnt[i], 1.0f);
}

__global__ void fill_kernel(const int* __restrict__ src, const int* __restrict__ dst,
                            int* __restrict__ cur, int* __restrict__ adj, int E) {
    int e = blockIdx.x * blockDim.x + threadIdx.x;
    if (e >= E) return;
    int d = dst[e];
    int pos = atomicAdd(&cur[d], 1);
    adj[pos] = src[e];
}

// ---------------- tf32 helpers ----------------
__device__ __forceinline__ uint2 split_tf32(float x) {
    unsigned hi, lo;
    asm("cvt.rna.tf32.f32 %0, %1;" : "=r"(hi) : "f"(x));
    float r = x - __uint_as_float(hi);
    asm("cvt.rna.tf32.f32 %0, %1;" : "=r"(lo) : "f"(r));
    return make_uint2(hi, lo);
}

__device__ __forceinline__ void mma8(float* d, unsigned a0, unsigned a1,
                                     unsigned a2, unsigned a3,
                                     unsigned b0, unsigned b1) {
    asm volatile(
        "mma.sync.aligned.m16n8k8.row.col.f32.tf32.tf32.f32 "
        "{%0,%1,%2,%3}, {%4,%5,%6,%7}, {%8,%9}, {%0,%1,%2,%3};"
        : "+f"(d[0]), "+f"(d[1]), "+f"(d[2]), "+f"(d[3])
        : "r"(a0), "r"(a1), "r"(a2), "r"(a3), "r"(b0), "r"(b1));
}

// ---------------- tensor-core dual-output GEMM (2-term tf32 split) ----------------
#define TBK 16
#define SROW 18
#define ATILE (128 * SROW)

__device__ __forceinline__ void stash(uint2* base, int row, int kq, float4 v) {
    uint2* p = base + row * SROW + kq * 4;
    p[0] = split_tf32(v.x);
    p[1] = split_tf32(v.y);
    p[2] = split_tf32(v.z);
    p[3] = split_tf32(v.w);
}

__global__ __launch_bounds__(256, 2) void gemm_dual_tc(
    const float* __restrict__ A, int lda, int K,
    const float* __restrict__ Wt, const float* __restrict__ Wb, int wld,
    float* __restrict__ Ot, float* __restrict__ Ob, int nNodes)
{
    extern __shared__ uint2 smem_u2[];
    uint2* Ash = smem_u2;
    uint2* Wsh = smem_u2 + 2 * ATILE;

    const int t = threadIdx.x;
    const int lane = t & 31, warp = t >> 5;
    const int grp = lane >> 2, tig = lane & 3;
    const int warpM = warp >> 1, warpN = warp & 1;
    const int m0 = blockIdx.x * 128;

    const int lm = t >> 2;
    const int lkq = t & 3;
    const int ar0 = min(m0 + lm, nNodes - 1);
    const int ar1 = min(m0 + lm + 64, nNodes - 1);
    const float* aptr0 = A + (size_t)ar0 * lda + lkq * 4;
    const float* aptr1 = A + (size_t)ar1 * lda + lkq * 4;
    const float* wptr0 = Wt + (size_t)lm * wld + lkq * 4;
    const float* wptr1 = Wb + (size_t)lm * wld + lkq * 4;

    float acc[2][8][4];
#pragma unroll
    for (int mt = 0; mt < 2; mt++)
#pragma unroll
        for (int nt = 0; nt < 8; nt++)
#pragma unroll
            for (int j = 0; j < 4; j++) acc[mt][nt][j] = 0.f;

    const int ntiles = K / TBK;

    float4 pa0 = *(const float4*)(aptr0);
    float4 pa1 = *(const float4*)(aptr1);
    float4 pw0 = *(const float4*)(wptr0);
    float4 pw1 = *(const float4*)(wptr1);
    stash(Ash, lm, lkq, pa0);
    stash(Ash, lm + 64, lkq, pa1);
    stash(Wsh, lm, lkq, pw0);
    stash(Wsh, lm + 64, lkq, pw1);
    __syncthreads();

    for (int tt = 0; tt < ntiles; tt++) {
        const int cur = tt & 1;
        const bool more = (tt + 1 < ntiles);
        if (more) {
            const int ko = (tt + 1) * TBK;
            pa0 = *(const float4*)(aptr0 + ko);
            pa1 = *(const float4*)(aptr1 + ko);
            pw0 = *(const float4*)(wptr0 + ko);
            pw1 = *(const float4*)(wptr1 + ko);
        }
        const uint2* Ab = Ash + cur * ATILE;
        const uint2* Wc = Wsh + cur * ATILE;
#pragma unroll
        for (int ks = 0; ks < 2; ks++) {
            const int kb = ks * 8;
            uint2 af[2][4];
#pragma unroll
            for (int mt = 0; mt < 2; mt++) {
                const uint2* ap = Ab + (warpM * 32 + mt * 16 + grp) * SROW + kb + tig;
                af[mt][0] = ap[0];
                af[mt][1] = ap[8 * SROW];
                af[mt][2] = ap[4];
                af[mt][3] = ap[8 * SROW + 4];
            }
#pragma unroll
            for (int nt = 0; nt < 8; nt++) {
                const uint2* wp = Wc + (warpN * 64 + nt * 8 + grp) * SROW + kb + tig;
                const uint2 b0 = wp[0];
                const uint2 b1 = wp[4];
#pragma unroll
                for (int mt = 0; mt < 2; mt++) {
                    // 2-term split: ah*bh + al*bh
                    mma8(acc[mt][nt], af[mt][0].x, af[mt][1].x, af[mt][2].x, af[mt][3].x, b0.x, b1.x);
                    mma8(acc[mt][nt], af[mt][0].y, af[mt][1].y, af[mt][2].y, af[mt][3].y, b0.x, b1.x);
                }
            }
        }
        if (more) {
            const int nxt = cur ^ 1;
            stash(Ash + nxt * ATILE, lm, lkq, pa0);
            stash(Ash + nxt * ATILE, lm + 64, lkq, pa1);
            stash(Wsh + nxt * ATILE, lm, lkq, pw0);
            stash(Wsh + nxt * ATILE, lm + 64, lkq, pw1);
        }
        __syncthreads();
    }

    float* O = warpN ? Ob : Ot;
#pragma unroll
    for (int mt = 0; mt < 2; mt++) {
#pragma unroll
        for (int nt = 0; nt < 8; nt++) {
            const int r0 = m0 + warpM * 32 + mt * 16 + grp;
            const int r1 = r0 + 8;
            const int col = nt * 8 + tig * 2;
            if (r0 < nNodes)
                *(float2*)(O + (size_t)r0 * 64 + col) = make_float2(acc[mt][nt][0], acc[mt][nt][1]);
            if (r1 < nNodes)
                *(float2*)(O + (size_t)r1 * 64 + col) = make_float2(acc[mt][nt][2], acc[mt][nt][3]);
        }
    }
}

#define GEMM_SMEM (4 * ATILE * (int)sizeof(uint2))   // 73728 bytes

// ---------------- CSR gather + combine (R3's pipelined form) ----------------
__global__ __launch_bounds__(256) void gather_combine(
    const float* __restrict__ P, const int* __restrict__ adj,
    const int* __restrict__ off, const int* __restrict__ cnt,
    const float* __restrict__ deginv, const float* __restrict__ R,
    const float* __restrict__ bl, float* __restrict__ H, int col, int n)
{
    int tid = blockIdx.x * blockDim.x + threadIdx.x;
    int nn = tid >> 4;
    int q  = tid & 15;
    if (nn >= n) return;
    const int beg = __ldg(off + nn);
    const int c   = __ldg(cnt + nn);
    const float4* Pq = (const float4*)P + q;

    float4 acc = make_float4(0.f, 0.f, 0.f, 0.f);
    int s0 = (c > 0) ? __ldg(adj + beg) : 0;
    for (int j = 0; j < c; j++) {
        int s1 = (j + 1 < c) ? __ldg(adj + beg + j + 1) : 0;
        float4 v = __ldg(Pq + (size_t)s0 * 16);
        acc.x += v.x; acc.y += v.y; acc.z += v.z; acc.w += v.w;
        s0 = s1;
    }
    const float di = __ldg(deginv + nn);
    const float4 r = *(const float4*)(R + (size_t)nn * 64 + q * 4);
    const float4 b = *(const float4*)(bl + q * 4);
    float4 h;
    h.x = fmaxf(fmaf(acc.x, di, b.x) + r.x, 0.f);
    h.y = fmaxf(fmaf(acc.y, di, b.y) + r.y, 0.f);
    h.z = fmaxf(fmaf(acc.z, di, b.z) + r.z, 0.f);
    h.w = fmaxf(fmaf(acc.w, di, b.w) + r.w, 0.f);
    *(float4*)(H + (size_t)nn * 192 + col + q * 4) = h;
}

// ---------------- edge head ----------------
__global__ __launch_bounds__(256) void edge_kernel(
    const float* __restrict__ U, const float* __restrict__ V,
    const int* __restrict__ src, const int* __restrict__ dst,
    const float* __restrict__ bm1, const float* __restrict__ Wm2,
    const float* __restrict__ bm2, float* __restrict__ out, int E)
{
    __shared__ float bsh[64];
    __shared__ float wsh[64];
    int t = threadIdx.x;
    if (t < 64)       bsh[t]      = bm1[t];
    else if (t < 128) wsh[t - 64] = Wm2[t - 64];
    __syncthreads();

    int e = blockIdx.x * blockDim.x + t;
    if (e >= E) return;
    int s = __ldg(src + e);
    int d = __ldg(dst + e);
    const float4* up = (const float4*)(U + (size_t)s * 64);
    const float4* vp = (const float4*)(V + (size_t)d * 64);
    float acc = __ldg(bm2);
#pragma unroll 4
    for (int j = 0; j < 16; j++) {
        float4 u = __ldg(up + j);
        float4 v = __ldg(vp + j);
        float4 b = *(const float4*)&bsh[j * 4];
        float4 w = *(const float4*)&wsh[j * 4];
        acc += fmaxf(u.x + v.x + b.x, 0.f) * w.x;
        acc += fmaxf(u.y + v.y + b.y, 0.f) * w.y;
        acc += fmaxf(u.z + v.z + b.z, 0.f) * w.z;
        acc += fmaxf(u.w + v.w + b.w, 0.f) * w.w;
    }
    out[e] = acc;
}

// ---------------- host launcher ----------------
extern "C" void kernel_launch(void* const* d_in, const int* in_sizes, int n_in,
                              void* d_out, int out_size)
{
    const float* x   = (const float*)d_in[0];
    const int*   src = (const int*)d_in[1];
    const int*   dst = (const int*)d_in[2];
    const float* Wl0 = (const float*)d_in[3];
    const float* bl0 = (const float*)d_in[4];
    const float* Wr0 = (const float*)d_in[5];
    const float* Wl1 = (const float*)d_in[6];
    const float* bl1 = (const float*)d_in[7];
    const float* Wr1 = (const float*)d_in[8];
    const float* Wl2 = (const float*)d_in[9];
    const float* bl2 = (const float*)d_in[10];
    const float* Wr2 = (const float*)d_in[11];
    const float* Wm1 = (const float*)d_in[12];
    const float* bm1 = (const float*)d_in[13];
    const float* Wm2 = (const float*)d_in[14];
    const float* bm2 = (const float*)d_in[15];
    float* out = (float*)d_out;
    const int E = in_sizes[1];

    void* p;
    cudaGetSymbolAddress(&p, g_P);      float* P      = (float*)p;
    cudaGetSymbolAddress(&p, g_R);      float* R      = (float*)p;
    cudaGetSymbolAddress(&p, g_H);      float* H      = (float*)p;
    cudaGetSymbolAddress(&p, g_U);      float* U      = (float*)p;
    cudaGetSymbolAddress(&p, g_V);      float* V      = (float*)p;
    cudaGetSymbolAddress(&p, g_deginv); float* deginv = (float*)p;
    cudaGetSymbolAddress(&p, g_cnt);    int*   cnt    = (int*)p;
    cudaGetSymbolAddress(&p, g_off);    int*   off    = (int*)p;
    cudaGetSymbolAddress(&p, g_cur);    int*   cur    = (int*)p;
    cudaGetSymbolAddress(&p, g_bsum);   int*   bsum   = (int*)p;
    cudaGetSymbolAddress(&p, g_adj);    int*   adj    = (int*)p;

    cudaFuncSetAttribute(gemm_dual_tc, cudaFuncAttributeMaxDynamicSharedMemorySize, GEMM_SMEM);

    const int T = 256;
    const int gemm_blocks = (N_NODES + 127) / 128;
    const int gc_blocks   = (N_NODES * 16 + T - 1) / T;

    // ---- CSR build (parallel scan) ----
    zero_int_kernel<<<(N_NODES + T - 1) / T, T>>>(cnt, N_NODES);
    count_deg_kernel<<<(E + T - 1) / T, T>>>(dst, cnt, E);
    scan1_kernel<<<NSCAN_BLOCKS, SCAN_T>>>(cnt, off, bsum, N_NODES);
    scan2_kernel<<<1, 128>>>(bsum, NSCAN_BLOCKS);
    scan3_kernel<<<(N_NODES + T - 1) / T, T>>>(off, cur, cnt, bsum, deginv, N_NODES);
    fill_kernel<<<(E + T - 1) / T, T>>>(src, dst, cur, adj, E);

    // ---- SAGE layer 0 ----
    gemm_dual_tc<<<gemm_blocks, 256, GEMM_SMEM>>>(x, 128, 128, Wl0, Wr0, 128, P, R, N_NODES);
    gather_combine<<<gc_blocks, T>>>(P, adj, off, cnt, deginv, R, bl0, H, 0, N_NODES);

    // ---- SAGE layer 1 ----
    gemm_dual_tc<<<gemm_blocks, 256, GEMM_SMEM>>>(H, 192, 64, Wl1, Wr1, 64, P, R, N_NODES);
    gather_combine<<<gc_blocks, T>>>(P, adj, off, cnt, deginv, R, bl1, H, 64, N_NODES);

    // ---- SAGE layer 2 ----
    gemm_dual_tc<<<gemm_blocks, 256, GEMM_SMEM>>>(H + 64, 192, 64, Wl2, Wr2, 64, P, R, N_NODES);
    gather_combine<<<gc_blocks, T>>>(P, adj, off, cnt, deginv, R, bl2, H, 128, N_NODES);

    // ---- edge MLP decomposition ----
    gemm_dual_tc<<<gemm_blocks, 256, GEMM_SMEM>>>(H, 192, 192, Wm1, Wm1 + 192, 384, U, V, N_NODES);

    // ---- per-edge head ----
    edge_kernel<<<(E + T - 1) / T, T>>>(U, V, src, dst, bm1, Wm2, bm2, out, E);
}